// round 13
// baseline (speedup 1.0000x reference)
#include <cuda_runtime.h>

// Problem constants (STGNN_91242285236402): B=8, T=16, N=64, F=16, H=128
#define Bc 8
#define Tc 16
#define Nc 64
#define Fc 16
#define Hc 128
#define BN (Bc * Nc)   // 512
#define GRID 128
#define NTHR 256

// Scratch (allocation-free): btT in k-vectorized layout [b][k>>2][n][k&3]
__device__ float g_bt4[Bc * 32 * Nc * 4];
__device__ unsigned g_bar = 0;          // grid barrier (monotonic, replay-safe)

// ---------------------------------------------------------------------------
// One fused kernel, 128 blocks x 256 threads (all co-resident on 148 SMs).
// Block (b = blockIdx>>4, g = blockIdx&15) owns rows rowbase = blockIdx*4,
// which are BOTH its Phase-A produce set and its Phase-B source nodes.
//   pre-arrive : node[4][128]; btT GEMM (W1t) -> g_bt4 (global)
//   arrive     : grid-barrier ticket (proven monotonic pattern)
//   hidden work: a GEMM (W1s) -> smem; wvec partials (vectorized); lp (cb
//                folded); w2 stage; pr init
//   wait       : spin to wave target
//   post       : dense edge loop reading g_bt4 DIRECTLY (coalesced L2 hits):
//     ew(s,t) = b2 + sum_k relu(a[s,k] + btT[k,t]) * W2[k], e = s*63+(t-(t>s))
//     pressures[b,t] += ew * lp[s]
// ---------------------------------------------------------------------------
__global__ void __launch_bounds__(NTHR, 1) kfused(
    const float* __restrict__ x,   const float* __restrict__ Wg,
    const float* __restrict__ bg,  const float* __restrict__ W1,
    const float* __restrict__ b1,  const float* __restrict__ W2,
    const float* __restrict__ b2,  const float* __restrict__ Wgcn,
    const float* __restrict__ bgcn,const float* __restrict__ Wp,
    const float* __restrict__ bp,  float* __restrict__ out, int E)
{
    __shared__ float x_sh[4][Fc];
    __shared__ float node_sh[4][Hc];
    __shared__ float a_sh[4][Hc];
    __shared__ float wv8[8][Hc];    // wvec partials per 16-k group (4 KB)
    __shared__ float w2_sh[Hc];
    __shared__ float lp_sh[4];
    __shared__ float pr_sh[Nc];
    __shared__ unsigned s_target;

    const int tid = threadIdx.x;
    const int b = blockIdx.x >> 4;
    const int g = blockIdx.x & 15;
    const int rowbase = blockIdx.x * 4;   // = b*64 + g*4

    // ---- stage x (4 rows x 16 f); init pressures (g==0 blocks)
    if (tid < 64) {
        int r = tid >> 4, f = tid & 15;
        int n = (rowbase + r) & 63;
        x_sh[r][f] = x[(((b * Tc + (Tc - 1)) * Nc + n) * Fc) + f];
    }
    if (g == 0 && tid < Nc) out[b * Nc + tid] = __ldg(bp);
    __syncthreads();

    // ---- node: 4 rows x 128 h over 256 threads (2 outputs each)
    #pragma unroll
    for (int i = 0; i < 2; i++) {
        int idx = tid + i * NTHR;
        int r = idx >> 7, h = idx & 127;
        const float4* wg4 = (const float4*)(Wg + h * Fc);
        float4 w0 = __ldg(wg4 + 0), w1 = __ldg(wg4 + 1);
        float4 w2v= __ldg(wg4 + 2), w3 = __ldg(wg4 + 3);
        const float* xr = x_sh[r];
        float acc = __ldg(&bg[h]);
        acc += xr[0]*w0.x + xr[1]*w0.y + xr[2]*w0.z + xr[3]*w0.w;
        acc += xr[4]*w1.x + xr[5]*w1.y + xr[6]*w1.z + xr[7]*w1.w;
        acc += xr[8]*w2v.x+ xr[9]*w2v.y+ xr[10]*w2v.z+ xr[11]*w2v.w;
        acc += xr[12]*w3.x+ xr[13]*w3.y+ xr[14]*w3.z+ xr[15]*w3.w;
        node_sh[r][h] = acc;
    }
    __syncthreads();

    // ---- cache node[4 rows][j*16..+16] in registers (16 float4)
    const int lane = tid & 31, w = tid >> 5;
    const int j = lane & 7, d = lane >> 3;
    float4 nr[4][4];
    #pragma unroll
    for (int r = 0; r < 4; r++)
        #pragma unroll
        for (int c = 0; c < 4; c++)
            nr[r][c] = *(const float4*)&node_sh[r][j * 16 + c * 4];

    // ---- btT GEMM (W1t half): warp w -> k in [w*16,+16); 8-lane dots
    {
        const float* Wt = W1 + Hc;   // W1t
        #pragma unroll
        for (int kk = 0; kk < 4; kk++) {
            int k = w * 16 + kk * 4 + d;
            const float4* wp4 = (const float4*)(Wt + k * (2 * Hc) + j * 16);
            float4 w0 = __ldg(wp4 + 0), w1 = __ldg(wp4 + 1);
            float4 w2v= __ldg(wp4 + 2), w3 = __ldg(wp4 + 3);
            #pragma unroll
            for (int r = 0; r < 4; r++) {
                float acc = nr[r][0].x*w0.x + nr[r][0].y*w0.y + nr[r][0].z*w0.z + nr[r][0].w*w0.w
                          + nr[r][1].x*w1.x + nr[r][1].y*w1.y + nr[r][1].z*w1.z + nr[r][1].w*w1.w
                          + nr[r][2].x*w2v.x+ nr[r][2].y*w2v.y+ nr[r][2].z*w2v.z+ nr[r][2].w*w2v.w
                          + nr[r][3].x*w3.x + nr[r][3].y*w3.y + nr[r][3].z*w3.z + nr[r][3].w*w3.w;
                acc += __shfl_xor_sync(0xffffffffu, acc, 1);
                acc += __shfl_xor_sync(0xffffffffu, acc, 2);
                acc += __shfl_xor_sync(0xffffffffu, acc, 4);
                if (j == 0) {
                    int n = g * 4 + r;
                    g_bt4[((b * 32 + (w * 4 + kk)) * Nc + n) * 4 + d] = acc;
                }
            }
        }
    }

    // ---- barrier ARRIVE (proven monotonic pattern, split arrive/wait)
    __syncthreads();                        // all g_bt4 stores issued
    if (tid == 0) {
        __threadfence();                    // publish before arrival
        unsigned v = atomicAdd(&g_bar, 1u);
        s_target = (v & ~(GRID - 1u)) + GRID;
    }

    // ---- hidden independent work: a GEMM (W1s) -> a_sh
    {
        const float* Ws = W1;   // W1s
        #pragma unroll
        for (int kk = 0; kk < 4; kk++) {
            int k = w * 16 + kk * 4 + d;
            const float4* wp4 = (const float4*)(Ws + k * (2 * Hc) + j * 16);
            float4 w0 = __ldg(wp4 + 0), w1 = __ldg(wp4 + 1);
            float4 w2v= __ldg(wp4 + 2), w3 = __ldg(wp4 + 3);
            #pragma unroll
            for (int r = 0; r < 4; r++) {
                float acc = nr[r][0].x*w0.x + nr[r][0].y*w0.y + nr[r][0].z*w0.z + nr[r][0].w*w0.w
                          + nr[r][1].x*w1.x + nr[r][1].y*w1.y + nr[r][1].z*w1.z + nr[r][1].w*w1.w
                          + nr[r][2].x*w2v.x+ nr[r][2].y*w2v.y+ nr[r][2].z*w2v.z+ nr[r][2].w*w2v.w
                          + nr[r][3].x*w3.x + nr[r][3].y*w3.y + nr[r][3].z*w3.z + nr[r][3].w*w3.w;
                acc += __shfl_xor_sync(0xffffffffu, acc, 1);
                acc += __shfl_xor_sync(0xffffffffu, acc, 2);
                acc += __shfl_xor_sync(0xffffffffu, acc, 4);
                if (j == 0) a_sh[r][k] = acc + __ldg(&b1[k]);
            }
        }
    }

    // ---- wvec partials, vectorized: thread = (kq = tid>>5, hq = tid&31)
    {
        int hq = tid & 31, kq = tid >> 5;
        const int k0 = kq * 16;
        float4 s = make_float4(0.f, 0.f, 0.f, 0.f);
        #pragma unroll
        for (int k = 0; k < 16; k++) {
            float wp = __ldg(&Wp[k0 + k]);
            float4 gv = __ldg((const float4*)(Wgcn + (k0 + k) * Hc) + hq);
            s.x += wp * gv.x; s.y += wp * gv.y;
            s.z += wp * gv.z; s.w += wp * gv.w;
        }
        *(float4*)&wv8[kq][hq * 4] = s;
    }
    if (tid < 128) w2_sh[tid] = __ldg(&W2[tid]);
    if (tid < Nc)  pr_sh[tid] = 0.f;
    __syncthreads();

    // lp: warps 0..3 reduce node rows 0..3 against wvec; cb folded inline
    if (w < 4) {
        int h4 = lane * 4;
        float4 n = *(const float4*)&node_sh[w][h4];
        float4 q = *(const float4*)&wv8[0][h4];
        #pragma unroll
        for (int kq = 1; kq < 8; kq++) {
            float4 t = *(const float4*)&wv8[kq][h4];
            q.x += t.x; q.y += t.y; q.z += t.z; q.w += t.w;
        }
        float4 wp = __ldg((const float4*)(Wp   + h4));
        float4 bc = __ldg((const float4*)(bgcn + h4));
        float p0 = n.x*q.x + wp.x*bc.x, p1 = n.y*q.y + wp.y*bc.y;
        float p2 = n.z*q.z + wp.z*bc.z, p3 = n.w*q.w + wp.w*bc.w;
        float v = (p0 + p1) + (p2 + p3);
        #pragma unroll
        for (int o = 16; o; o >>= 1) v += __shfl_xor_sync(0xffffffffu, v, o);
        if (lane == 0) lp_sh[w] = v;
    }

    // ---- barrier WAIT
    __syncthreads();                        // s_target visible; local work done
    if (tid == 0) {
        volatile unsigned* p = &g_bar;
        while (*p < s_target) __nanosleep(32);
        __threadfence();                    // acquire
    }
    __syncthreads();

    // ---- dense edge loop: warp = (sl = w>>1, th = w&1); lane -> t
    //      bt read DIRECTLY from g_bt4 (coalesced float4 per kq, L2 hits)
    {
        const int sl = w >> 1;
        const int t  = (w & 1) * 32 + lane;
        const int s  = g * 4 + sl;
        const float4* btp = (const float4*)g_bt4 + (b * 32) * Nc + t;
        const float b2v = __ldg(b2);

        float acc = 0.f;
        #pragma unroll 16
        for (int kq = 0; kq < 32; kq++) {
            float4 a4 = *(const float4*)&a_sh[sl][kq * 4];    // broadcast
            float4 w4 = *(const float4*)&w2_sh[kq * 4];       // broadcast
            float4 bt = __ldg(btp + kq * Nc);                 // coalesced
            acc += fmaxf(a4.x + bt.x, 0.f) * w4.x;
            acc += fmaxf(a4.y + bt.y, 0.f) * w4.y;
            acc += fmaxf(a4.z + bt.z, 0.f) * w4.z;
            acc += fmaxf(a4.w + bt.w, 0.f) * w4.w;
        }

        if (t != s) {
            float ew = acc + b2v;
            int e = s * 63 + (t < s ? t : t - 1);
            out[BN + b * E + e] = ew;
            atomicAdd(&pr_sh[t], ew * lp_sh[sl]);
        }
    }
    __syncthreads();
    if (tid < Nc) atomicAdd(out + b * Nc + tid, pr_sh[tid]);
}

// ---------------------------------------------------------------------------
extern "C" void kernel_launch(void* const* d_in, const int* in_sizes, int n_in,
                              void* d_out, int out_size)
{
    const float* x    = (const float*)d_in[0];
    const float* Wg   = (const float*)d_in[2];
    const float* bg   = (const float*)d_in[3];
    const float* W1   = (const float*)d_in[4];
    const float* b1   = (const float*)d_in[5];
    const float* W2   = (const float*)d_in[6];
    const float* b2   = (const float*)d_in[7];
    const float* Wgcn = (const float*)d_in[8];
    const float* bgcn = (const float*)d_in[9];
    const float* Wp   = (const float*)d_in[14];
    const float* bp   = (const float*)d_in[15];
    float* out = (float*)d_out;

    const int E = in_sizes[1] / 2;   // 4032 = 64*63 (dense permutations)

    kfused<<<GRID, NTHR>>>(x, Wg, bg, W1, b1, W2, b2,
                           Wgcn, bgcn, Wp, bp, out, E);
}

// round 14
// speedup vs baseline: 1.2208x; 1.2208x over previous
#include <cuda_runtime.h>

// Problem constants (STGNN_91242285236402): B=8, T=16, N=64, F=16, H=128
#define Bc 8
#define Tc 16
#define Nc 64
#define Fc 16
#define Hc 128
#define BN (Bc * Nc)   // 512
#define GRID 128
#define NTHR 256

// Folded-weight scratch (allocation-free, 16B-aligned for float4 loads)
__device__ __align__(16) float g_Ms[Hc * Fc];   // M_s[k][f] = sum_h W1s[k][h]*Wg[h][f]
__device__ __align__(16) float g_Mt[Hc * Fc];   // M_t[k][f] = sum_h W1t[k][h]*Wg[h][f]
__device__ __align__(16) float g_ca[Hc];        // b1[k] + W1s[k]·bg
__device__ __align__(16) float g_ct[Hc];        // W1t[k]·bg
__device__ __align__(16) float g_wvec[Hc];      // Wgcn.T @ Wp
__device__ unsigned g_bar = 0;                  // grid barrier (monotonic, replay-safe)

__device__ __forceinline__ float dot16v(const float4* a, const float4* b)
{
    float p0 = a[0].x*b[0].x + a[0].y*b[0].y + a[0].z*b[0].z + a[0].w*b[0].w;
    float p1 = a[1].x*b[1].x + a[1].y*b[1].y + a[1].z*b[1].z + a[1].w*b[1].w;
    float p2 = a[2].x*b[2].x + a[2].y*b[2].y + a[2].z*b[2].z + a[2].w*b[2].w;
    float p3 = a[3].x*b[3].x + a[3].y*b[3].y + a[3].z*b[3].z + a[3].w*b[3].w;
    return (p0 + p1) + (p2 + p3);
}

// ---------------------------------------------------------------------------
// One fused kernel, 128 blocks x 256 threads (all co-resident).
// PRE-barrier (block i): compute row k=i of M_s/M_t (+ca/ct/wvec[k]); stage
//   x[b]; compute node rows (for lp); blocks 0..7 init pressures.
// Barrier: proven monotonic arrive/spin.
// POST-barrier (b = i>>4, g = i&15):
//   stage M_t (8KB) + ct; a[4][128] from M_s (16-MAC dots); lp from wvec;
//   bt[k][t] for ALL 64 t locally from x & M_t (16-MAC) -> smem;
//   dense edge loop (R8 form):
//     ew(s,t) = b2 + sum_k relu(a[s,k] + bt[k,t])*W2[k], e = s*63+(t-(t>s))
//     pressures[b,t] += ew*lp[s]
// ---------------------------------------------------------------------------
__global__ void __launch_bounds__(NTHR, 1) kfused(
    const float* __restrict__ x,   const float* __restrict__ Wg,
    const float* __restrict__ bg,  const float* __restrict__ W1,
    const float* __restrict__ b1,  const float* __restrict__ W2,
    const float* __restrict__ b2,  const float* __restrict__ Wgcn,
    const float* __restrict__ bgcn,const float* __restrict__ Wp,
    const float* __restrict__ bp,  float* __restrict__ out, int E)
{
    // bt4 region (32KB) is reused: pre-barrier it holds pm + node.
    __shared__ union {
        float bt4[32][Nc][4];                 // [k>>2][t][k&3]
        struct {
            float pm[2][8][17];               // M partials (padded)
            float node[4][Hc];                // node rows for lp
        } pre;
    } u;
    __shared__ float x_sh[Nc * Fc];           // 4KB  [n][f]
    __shared__ float a_sh[4][Hc];             // 2KB
    __shared__ float Mt_sh[Hc * Fc];          // 8KB  [k][f]
    __shared__ float ct_sh[Hc];
    __shared__ float w2_sh[Hc];
    __shared__ float lp_sh[4];
    __shared__ float pr_sh[Nc];
    __shared__ unsigned s_target;

    const int tid = threadIdx.x;
    const int i = blockIdx.x;
    const int b = i >> 4, g = i & 15;
    const int k = i;                          // this block's M row
    const int lane = tid & 31, w = tid >> 5;

    // ================= PRE-BARRIER =================
    // stage x[b, T-1] (64x16 floats = 256 float4, coalesced)
    {
        const float4* xs = (const float4*)(x + (size_t)((b * Tc + (Tc - 1)) * Nc) * Fc);
        ((float4*)x_sh)[tid] = __ldg(xs + tid);
    }
    if (tid < Hc) w2_sh[tid] = __ldg(&W2[tid]);
    if (tid < Nc) pr_sh[tid] = 0.f;
    if (i < Bc && tid < Nc) out[i * Nc + tid] = __ldg(bp);   // pressures init

    // M partials: side = tid>>7 (0:M_s, 1:M_t), f = tid&15, hg = (tid>>4)&7
    {
        const int side = tid >> 7;
        const int f = tid & 15;
        const int hg = (tid >> 4) & 7;
        const float* w1r = W1 + k * (2 * Hc) + side * Hc + hg * 16;
        const float* wgp = Wg + (hg * 16) * Fc + f;
        float s0 = 0.f, s1 = 0.f, s2 = 0.f, s3 = 0.f;
        #pragma unroll
        for (int e = 0; e < 16; e += 4) {
            s0 += __ldg(w1r + e + 0) * __ldg(wgp + (e + 0) * Fc);
            s1 += __ldg(w1r + e + 1) * __ldg(wgp + (e + 1) * Fc);
            s2 += __ldg(w1r + e + 2) * __ldg(wgp + (e + 2) * Fc);
            s3 += __ldg(w1r + e + 3) * __ldg(wgp + (e + 3) * Fc);
        }
        u.pre.pm[side][hg][f] = (s0 + s1) + (s2 + s3);
    }
    __syncthreads();

    // node rows (for lp): 4 rows x 128 h, 2 outputs/thread
    #pragma unroll
    for (int it = 0; it < 2; it++) {
        int idx = tid + it * NTHR;
        int rl = idx >> 7, h = idx & 127;
        const float4* wg4 = (const float4*)(Wg + h * Fc);
        float4 wv[4] = { __ldg(wg4), __ldg(wg4+1), __ldg(wg4+2), __ldg(wg4+3) };
        const float4* xr = (const float4*)(x_sh + (g * 4 + rl) * Fc);
        float4 xv[4] = { xr[0], xr[1], xr[2], xr[3] };
        u.pre.node[rl][h] = __ldg(&bg[h]) + dot16v(xv, wv);
    }

    // specialized finishing: warp0 M-reduce; warp2 ca/ct; warp3 wvec[k]
    if (w == 0) {
        int side = lane >> 4, f = lane & 15;
        float m = 0.f;
        #pragma unroll
        for (int hg = 0; hg < 8; hg++) m += u.pre.pm[side][hg][f];
        if (side == 0) g_Ms[k * 16 + f] = m;
        else           g_Mt[k * 16 + f] = m;
    } else if (w == 2) {
        int side = lane >> 4;
        int h0 = (lane & 15) * 8;
        const float* w1r = W1 + k * (2 * Hc) + side * Hc + h0;
        float s = 0.f;
        #pragma unroll
        for (int e = 0; e < 8; e++) s += __ldg(&bg[h0 + e]) * __ldg(w1r + e);
        s += __shfl_xor_sync(0xffffffffu, s, 1);
        s += __shfl_xor_sync(0xffffffffu, s, 2);
        s += __shfl_xor_sync(0xffffffffu, s, 4);
        s += __shfl_xor_sync(0xffffffffu, s, 8);
        if ((lane & 15) == 0) {
            if (side == 0) g_ca[k] = s + __ldg(&b1[k]);
            else           g_ct[k] = s;
        }
    } else if (w == 3) {
        float s = 0.f;
        #pragma unroll
        for (int e = 0; e < 4; e++)
            s += __ldg(&Wp[lane * 4 + e]) * __ldg(&Wgcn[(lane * 4 + e) * Hc + k]);
        #pragma unroll
        for (int o = 16; o; o >>= 1) s += __shfl_xor_sync(0xffffffffu, s, o);
        if (lane == 0) g_wvec[k] = s;
    }

    // ---- barrier (proven monotonic pattern)
    __syncthreads();
    if (tid == 0) {
        __threadfence();
        unsigned v = atomicAdd(&g_bar, 1u);
        s_target = (v & ~(GRID - 1u)) + GRID;
    }
    __syncthreads();
    if (tid == 0) {
        volatile unsigned* p = &g_bar;
        while (*p < s_target) __nanosleep(32);
        __threadfence();
    }
    __syncthreads();

    // ================= POST-BARRIER =================
    // stage M_t (512 float4) + ct
    {
        const float4* src = (const float4*)g_Mt;
        ((float4*)Mt_sh)[tid]       = __ldg(src + tid);
        ((float4*)Mt_sh)[tid + 256] = __ldg(src + tid + 256);
    }
    if (tid < Hc) ct_sh[tid] = __ldg(&g_ct[tid]);

    // a[rl][k2] = ca[k2] + x[src]·M_s[k2]  (2 rows per thread)
    {
        int k2 = tid & 127, rr = tid >> 7;
        const float4* ms = (const float4*)(g_Ms + k2 * 16);
        float4 mv[4] = { __ldg(ms), __ldg(ms+1), __ldg(ms+2), __ldg(ms+3) };
        float cav = __ldg(&g_ca[k2]);
        #pragma unroll
        for (int rp = 0; rp < 2; rp++) {
            int rl = rr + rp * 2;
            const float4* xr = (const float4*)(x_sh + (g * 4 + rl) * Fc);
            float4 xv[4] = { xr[0], xr[1], xr[2], xr[3] };
            a_sh[rl][k2] = cav + dot16v(xv, mv);
        }
    }

    // lp: warps 0..3 reduce node rows vs wvec, cb (Wp·bgcn) folded inline
    if (w < 4) {
        int h4 = lane * 4;
        float4 n  = *(const float4*)&u.pre.node[w][h4];
        float4 q  = __ldg((const float4*)(g_wvec + h4));
        float4 wp = __ldg((const float4*)(Wp    + h4));
        float4 bc = __ldg((const float4*)(bgcn  + h4));
        float p0 = n.x*q.x + wp.x*bc.x, p1 = n.y*q.y + wp.y*bc.y;
        float p2 = n.z*q.z + wp.z*bc.z, p3 = n.w*q.w + wp.w*bc.w;
        float v = (p0 + p1) + (p2 + p3);
        #pragma unroll
        for (int o = 16; o; o >>= 1) v += __shfl_xor_sync(0xffffffffu, v, o);
        if (lane == 0) lp_sh[w] = v;
    }
    __syncthreads();   // a_sh, lp_sh, Mt_sh, ct_sh ready; node region now free

    // bt[k][t] for all t: warp w owns kq = w*4..w*4+3 (k = w*16..w*16+15)
    {
        float4 xa[2][4];
        #pragma unroll
        for (int th = 0; th < 2; th++)
            #pragma unroll
            for (int jj = 0; jj < 4; jj++)
                xa[th][jj] = *(const float4*)(x_sh + (th * 32 + lane) * Fc + jj * 4);

        #pragma unroll
        for (int kk = 0; kk < 4; kk++) {
            int kq = w * 4 + kk;
            float4 mt[4][4];
            float ctv[4];
            #pragma unroll
            for (int c = 0; c < 4; c++) {
                const float4* mr = (const float4*)(Mt_sh + (kq * 4 + c) * Fc);
                mt[c][0] = mr[0]; mt[c][1] = mr[1];
                mt[c][2] = mr[2]; mt[c][3] = mr[3];
                ctv[c] = ct_sh[kq * 4 + c];
            }
            #pragma unroll
            for (int th = 0; th < 2; th++) {
                float4 r;
                r.x = ctv[0] + dot16v(xa[th], mt[0]);
                r.y = ctv[1] + dot16v(xa[th], mt[1]);
                r.z = ctv[2] + dot16v(xa[th], mt[2]);
                r.w = ctv[3] + dot16v(xa[th], mt[3]);
                *(float4*)&u.bt4[kq][th * 32 + lane][0] = r;
            }
        }
    }
    __syncthreads();

    // dense edge loop (R8 form): warp = (sl = w>>1, th = w&1); lane -> t
    {
        const int sl = w >> 1;
        const int t  = (w & 1) * 32 + lane;
        const int s  = g * 4 + sl;
        const float b2v = __ldg(b2);

        float acc = 0.f;
        #pragma unroll 16
        for (int kq = 0; kq < 32; kq++) {
            float4 a4 = *(const float4*)&a_sh[sl][kq * 4];    // broadcast
            float4 w4 = *(const float4*)&w2_sh[kq * 4];       // broadcast
            float4 bt = *(const float4*)&u.bt4[kq][t][0];     // conflict-free
            acc += fmaxf(a4.x + bt.x, 0.f) * w4.x;
            acc += fmaxf(a4.y + bt.y, 0.f) * w4.y;
            acc += fmaxf(a4.z + bt.z, 0.f) * w4.z;
            acc += fmaxf(a4.w + bt.w, 0.f) * w4.w;
        }

        if (t != s) {
            float ew = acc + b2v;
            int e = s * 63 + (t < s ? t : t - 1);
            out[BN + b * E + e] = ew;
            atomicAdd(&pr_sh[t], ew * lp_sh[sl]);
        }
    }
    __syncthreads();
    if (tid < Nc) atomicAdd(out + b * Nc + tid, pr_sh[tid]);
}

// ---------------------------------------------------------------------------
extern "C" void kernel_launch(void* const* d_in, const int* in_sizes, int n_in,
                              void* d_out, int out_size)
{
    const float* x    = (const float*)d_in[0];
    const float* Wg   = (const float*)d_in[2];
    const float* bg   = (const float*)d_in[3];
    const float* W1   = (const float*)d_in[4];
    const float* b1   = (const float*)d_in[5];
    const float* W2   = (const float*)d_in[6];
    const float* b2   = (const float*)d_in[7];
    const float* Wgcn = (const float*)d_in[8];
    const float* bgcn = (const float*)d_in[9];
    const float* Wp   = (const float*)d_in[14];
    const float* bp   = (const float*)d_in[15];
    float* out = (float*)d_out;

    const int E = in_sizes[1] / 2;   // 4032 = 64*63 (dense permutations)

    kfused<<<GRID, NTHR>>>(x, Wg, bg, W1, b1, W2, b2,
                           Wgcn, bgcn, Wp, bp, out, E);
}